// round 1
// baseline (speedup 1.0000x reference)
#include <cuda_runtime.h>

// ---------------------------------------------------------------------------
// PlanStructuredNetwork: fused tree of small MLPs.
//   Leaf:  (B*1024, 32) -> 128 -> 128 -> 32
//   Join x10: (B*n, 96=feat32+child64) -> 128 -> 128 -> 32,  n = 512..1
//   Output: cur[:,0,0]  (B floats)
// fp32 SIMT baseline: per-level fused 3-layer MLP, 128-row tiles,
// weights staged in smem, 8x8 register micro-tiles.
// ---------------------------------------------------------------------------

#define NB    2048
#define NLEAF 1024
#define FD    32
#define HD    128
#define OD    32
#define IND   (FD + 2 * OD)   // 96, join input dim

#define TILE_R 128
#define BLK    256
#define AS     129            // activation smem row stride (conflict-free)

// Scratch (alloc-free rule: __device__ globals)
__device__ float g_bufA[(size_t)NB * NLEAF * OD];        // 268 MB
__device__ float g_bufB[(size_t)NB * (NLEAF / 2) * OD];  // 134 MB

// smem layout (floats)
#define XS_OFF 0
#define HS_OFF (TILE_R * AS)
#define WS_OFF (2 * TILE_R * AS)
#define BS_OFF (2 * TILE_R * AS + HD * HD)
#define SMEM_FLOATS (2 * TILE_R * AS + HD * HD + HD)
#define SMEM_BYTES (SMEM_FLOATS * 4)

__device__ __forceinline__ void copy_smem4(float* dst, const float* __restrict__ src,
                                           int n, int tid) {
    float4* d4 = reinterpret_cast<float4*>(dst);
    const float4* s4 = reinterpret_cast<const float4*>(src);
    for (int i = tid; i < (n >> 2); i += BLK) d4[i] = s4[i];
}

// One layer: Out[128 x N] = act(As[128 x K] @ Ws[K x N] + bs)
// thread (ty,tx): rows ty*8..+7, cols tx*TN..+TN-1
template <int K, int N, int TN, bool RELU, bool TO_SMEM>
__device__ __forceinline__ void layer_compute(const float* __restrict__ As,
                                              const float* __restrict__ Ws,
                                              const float* __restrict__ bs,
                                              float* __restrict__ out,
                                              int ty, int tx) {
    float acc[8][TN];
#pragma unroll
    for (int i = 0; i < 8; i++)
#pragma unroll
        for (int j = 0; j < TN; j++) acc[i][j] = 0.f;

    const float* arow = As + (ty * 8) * AS;
    const float* wcol = Ws + tx * TN;

#pragma unroll 4
    for (int k = 0; k < K; k++) {
        float a[8];
#pragma unroll
        for (int i = 0; i < 8; i++) a[i] = arow[i * AS + k];
        float w[TN];
        if (TN == 8) {
            const float4* wp = reinterpret_cast<const float4*>(wcol + k * N);
            float4 w0 = wp[0];
            float4 w1 = wp[1];
            w[0] = w0.x; w[1] = w0.y; w[2] = w0.z; w[3] = w0.w;
            w[4] = w1.x; w[5] = w1.y; w[6] = w1.z; w[7] = w1.w;
        } else {
#pragma unroll
            for (int j = 0; j < TN; j++) w[j] = wcol[k * N + j];
        }
#pragma unroll
        for (int i = 0; i < 8; i++)
#pragma unroll
            for (int j = 0; j < TN; j++) acc[i][j] = fmaf(a[i], w[j], acc[i][j]);
    }

    float bb[TN];
#pragma unroll
    for (int j = 0; j < TN; j++) bb[j] = bs[tx * TN + j];

#pragma unroll
    for (int i = 0; i < 8; i++) {
#pragma unroll
        for (int j = 0; j < TN; j++) {
            float v = acc[i][j] + bb[j];
            if (RELU) v = fmaxf(v, 0.f);
            if (TO_SMEM)
                out[(ty * 8 + i) * AS + tx * TN + j] = v;
            else
                out[(ty * 8 + i) * OD + tx * TN + j] = v;
        }
    }
}

// ---------------------------------------------------------------------------
__global__ void __launch_bounds__(BLK, 1)
leaf_kernel(const float* __restrict__ in,
            const float* __restrict__ W1, const float* __restrict__ b1,
            const float* __restrict__ W2, const float* __restrict__ b2,
            const float* __restrict__ W3, const float* __restrict__ b3) {
    extern __shared__ float smem[];
    float* Xs = smem + XS_OFF;
    float* Hs = smem + HS_OFF;
    float* Ws = smem + WS_OFF;
    float* bs = smem + BS_OFF;

    int tid = threadIdx.x;
    int ty = tid >> 4, tx = tid & 15;
    size_t row0 = (size_t)blockIdx.x * TILE_R;

    // gather X (coalesced read, conflict-free strided write)
    {
        const float* gsrc = in + row0 * FD;
        for (int idx = tid; idx < TILE_R * FD; idx += BLK) {
            int r = idx >> 5, k = idx & 31;
            Xs[r * AS + k] = gsrc[idx];
        }
    }
    copy_smem4(Ws, W1, FD * HD, tid);
    if (tid < HD) bs[tid] = b1[tid];
    __syncthreads();

    layer_compute<FD, HD, 8, true, true>(Xs, Ws, bs, Hs, ty, tx);
    __syncthreads();

    copy_smem4(Ws, W2, HD * HD, tid);
    if (tid < HD) bs[tid] = b2[tid];
    __syncthreads();

    layer_compute<HD, HD, 8, true, true>(Hs, Ws, bs, Xs, ty, tx);
    __syncthreads();

    copy_smem4(Ws, W3, HD * OD, tid);
    if (tid < OD) bs[tid] = b3[tid];
    __syncthreads();

    float* outp = g_bufA + row0 * OD;
    layer_compute<HD, OD, 2, false, false>(Xs, Ws, bs, outp, ty, tx);
}

// ---------------------------------------------------------------------------
__global__ void __launch_bounds__(BLK, 1)
join_kernel(const float* __restrict__ feats,
            const float* __restrict__ W1, const float* __restrict__ b1,
            const float* __restrict__ W2, const float* __restrict__ b2,
            const float* __restrict__ W3, const float* __restrict__ b3,
            int logn, int off, int src_is_A) {
    extern __shared__ float smem[];
    float* Xs = smem + XS_OFF;
    float* Hs = smem + HS_OFF;
    float* Ws = smem + WS_OFF;
    float* bs = smem + BS_OFF;

    int tid = threadIdx.x;
    int ty = tid >> 4, tx = tid & 15;
    int n = 1 << logn;
    int row0 = blockIdx.x * TILE_R;

    const float* prev = src_is_A ? g_bufA : g_bufB;
    float* dst = src_is_A ? g_bufB : g_bufA;

    // gather X = [internal_feats slice (32) | child pair (64, contiguous)]
    for (int idx = tid; idx < TILE_R * IND; idx += BLK) {
        int r = idx / IND;
        int k = idx - r * IND;
        int gr = row0 + r;
        int b = gr >> logn;
        int i = gr & (n - 1);
        float v;
        if (k < FD)
            v = feats[((b * (NLEAF - 1) + off + i) << 5) + k];
        else
            v = prev[(((size_t)(b << (logn + 1)) + 2 * i) << 5) + (k - FD)];
        Xs[r * AS + k] = v;
    }
    copy_smem4(Ws, W1, IND * HD, tid);
    if (tid < HD) bs[tid] = b1[tid];
    __syncthreads();

    layer_compute<IND, HD, 8, true, true>(Xs, Ws, bs, Hs, ty, tx);
    __syncthreads();

    copy_smem4(Ws, W2, HD * HD, tid);
    if (tid < HD) bs[tid] = b2[tid];
    __syncthreads();

    layer_compute<HD, HD, 8, true, true>(Hs, Ws, bs, Xs, ty, tx);
    __syncthreads();

    copy_smem4(Ws, W3, HD * OD, tid);
    if (tid < OD) bs[tid] = b3[tid];
    __syncthreads();

    float* outp = dst + (size_t)row0 * OD;
    layer_compute<HD, OD, 2, false, false>(Xs, Ws, bs, outp, ty, tx);
}

// ---------------------------------------------------------------------------
__global__ void extract_kernel(float* __restrict__ out) {
    int b = blockIdx.x * blockDim.x + threadIdx.x;
    if (b < NB) out[b] = g_bufA[(size_t)b * OD];  // final level lands in bufA
}

// ---------------------------------------------------------------------------
extern "C" void kernel_launch(void* const* d_in, const int* in_sizes, int n_in,
                              void* d_out, int out_size) {
    const float* leaf_feats = (const float*)d_in[0];
    const float* internal   = (const float*)d_in[1];
    const float* sW1 = (const float*)d_in[2];
    const float* sb1 = (const float*)d_in[3];
    const float* sW2 = (const float*)d_in[4];
    const float* sb2 = (const float*)d_in[5];
    const float* sW3 = (const float*)d_in[6];
    const float* sb3 = (const float*)d_in[7];
    const float* jW1 = (const float*)d_in[8];
    const float* jb1 = (const float*)d_in[9];
    const float* jW2 = (const float*)d_in[10];
    const float* jb2 = (const float*)d_in[11];
    const float* jW3 = (const float*)d_in[12];
    const float* jb3 = (const float*)d_in[13];
    float* out = (float*)d_out;

    cudaFuncSetAttribute(leaf_kernel, cudaFuncAttributeMaxDynamicSharedMemorySize, SMEM_BYTES);
    cudaFuncSetAttribute(join_kernel, cudaFuncAttributeMaxDynamicSharedMemorySize, SMEM_BYTES);

    // Leaf: writes g_bufA
    leaf_kernel<<<(NB * NLEAF) / TILE_R, BLK, SMEM_BYTES>>>(
        leaf_feats, sW1, sb1, sW2, sb2, sW3, sb3);

    // Join levels n = 512 .. 1, ping-pong A<->B (final result lands in A)
    int off = 0;
    int src_is_A = 1;
    for (int logn = 9; logn >= 0; --logn) {
        int n = 1 << logn;
        int blocks = (NB * n) / TILE_R;
        join_kernel<<<blocks, BLK, SMEM_BYTES>>>(
            internal, jW1, jb1, jW2, jb2, jW3, jb3, logn, off, src_is_A);
        off += n;
        src_is_A ^= 1;
    }

    extract_kernel<<<(NB + 255) / 256, 256>>>(out);
}

// round 3
// speedup vs baseline: 2.5651x; 2.5651x over previous
#include <cuda_runtime.h>
#include <cuda_bf16.h>
#include <cstdint>

// ---------------------------------------------------------------------------
// PlanStructuredNetwork via warp-level tensor cores (mma.sync bf16, fp32 acc),
// bf16x3 split (hi/lo) for fp32-grade precision. No tcgen05 (toolchain builds
// through compute_103 which rejects it); ldmatrix+mma.sync are baseline PTX.
//   Leaf:  (B*1024, 32) -> 128 -> 128 -> 32
//   Join x10: (B*n, 96) -> 128 -> 128 -> 32,  n = 512..1
// Persistent CTAs, 256 thr, 64-row tiles, all weights (hi/lo, transposed
// [N][K]) resident in smem; activations ping-pong in smem; accums in regs.
// ---------------------------------------------------------------------------

#define NB    2048
#define NLEAF 1024
#define FD    32
#define HD    128
#define OD    32

#define TILE_R  64
#define THREADS 256

__device__ float g_bufA[(size_t)NB * NLEAF * OD];        // 268 MB
__device__ float g_bufB[(size_t)NB * (NLEAF / 2) * OD];  // 134 MB

// --- smem byte offsets ---
// act strides: input = 208 B/row (104 bf16), hidden = 272 B/row (136 bf16)
#define AA_HI   0           // 64*272 = 17408
#define AA_LO   17408
#define AB_HI   34816
#define AB_LO   52224
#define W1T_HI  69632       // [128][104] bf16 = 26624 B
#define W1T_LO  96256
#define W2T_HI  122880      // [128][136] bf16 = 34816 B
#define W2T_LO  157696
#define W3T_HI  192512      // [32][136] bf16 = 8704 B
#define W3T_LO  201216
#define B1OFF   209920
#define B2OFF   210432
#define B3OFF   210944
#define SMEM_TOTAL 211072

#define AST_IN  208
#define AST_H   272
#define W1ST    208
#define W2ST    272
#define W3ST    272

// ---------------------------------------------------------------------------
__device__ __forceinline__ uint32_t smem_u32(const void* p) {
    uint32_t a;
    asm("{ .reg .u64 t; cvta.to.shared.u64 t, %1; cvt.u32.u64 %0, t; }"
        : "=r"(a) : "l"(p));
    return a;
}

#define LDSM_X4(r0, r1, r2, r3, addr)                                          \
    asm volatile("ldmatrix.sync.aligned.m8n8.x4.shared.b16 {%0,%1,%2,%3}, [%4];" \
                 : "=r"(r0), "=r"(r1), "=r"(r2), "=r"(r3) : "r"(addr))

#define MMA_BF16(c, a0, a1, a2, a3, b0, b1)                                    \
    asm volatile("mma.sync.aligned.m16n8k16.row.col.f32.bf16.bf16.f32 "        \
                 "{%0,%1,%2,%3}, {%4,%5,%6,%7}, {%8,%9}, {%0,%1,%2,%3};"       \
                 : "+f"((c)[0]), "+f"((c)[1]), "+f"((c)[2]), "+f"((c)[3])      \
                 : "r"(a0), "r"(a1), "r"(a2), "r"(a3), "r"(b0), "r"(b1))

__device__ __forceinline__ void split2(float v0, float v1, uint32_t& hi, uint32_t& lo) {
    __nv_bfloat16 h0 = __float2bfloat16(v0);
    __nv_bfloat16 h1 = __float2bfloat16(v1);
    float r0 = v0 - __bfloat162float(h0);
    float r1 = v1 - __bfloat162float(h1);
    __nv_bfloat16 l0 = __float2bfloat16(r0);
    __nv_bfloat16 l1 = __float2bfloat16(r1);
    hi = (uint32_t)__bfloat16_as_ushort(h0) | ((uint32_t)__bfloat16_as_ushort(h1) << 16);
    lo = (uint32_t)__bfloat16_as_ushort(l0) | ((uint32_t)__bfloat16_as_ushort(l1) << 16);
}

// ---------------------------------------------------------------------------
// One accumulation pass: C += A_plane[warp 16 rows x K] @ B_plane[cols x K]^T
// NPAIRS n-tile pairs of 16 cols (ldmatrix.x4 per pair).
// aAddr/bAddr are per-lane ldmatrix base addresses (k-chunk 0).
// ---------------------------------------------------------------------------
template <int NPAIRS>
__device__ __forceinline__ void gemm_pass(uint32_t aAddr, uint32_t bAddr,
                                          int nk, int bstB, float c[][4]) {
    for (int k = 0; k < nk; k++) {
        uint32_t a0, a1, a2, a3;
        LDSM_X4(a0, a1, a2, a3, aAddr + k * 32);
#pragma unroll
        for (int j = 0; j < NPAIRS; j++) {
            uint32_t b0, b1, b2, b3;
            LDSM_X4(b0, b1, b2, b3, bAddr + j * 16 * bstB + k * 32);
            MMA_BF16(c[2 * j],     a0, a1, a2, a3, b0, b1);
            MMA_BF16(c[2 * j + 1], a0, a1, a2, a3, b2, b3);
        }
    }
}

// 3-pass bf16x3 GEMM: C = AhiBhi + AhiBlo + AloBhi
template <int NPAIRS>
__device__ __forceinline__ void gemm3(uint32_t sb,
                                      uint32_t aHiOff, uint32_t aLoOff, int astB,
                                      uint32_t bHiOff, uint32_t bLoOff, int bstB,
                                      int nk, int colBase, int lane, int wm,
                                      float c[][4]) {
#pragma unroll
    for (int j = 0; j < 2 * NPAIRS; j++)
#pragma unroll
        for (int q = 0; q < 4; q++) c[j][q] = 0.f;

    int aRow = wm * 16 + (lane & 15);
    uint32_t aKb = (uint32_t)(lane >> 4) * 16;
    uint32_t aHi = sb + aHiOff + (uint32_t)aRow * astB + aKb;
    uint32_t aLo = sb + aLoOff + (uint32_t)aRow * astB + aKb;

    int nLoc = (lane & 7) + ((lane >> 4) << 3);
    uint32_t bKb = (uint32_t)((lane >> 3) & 1) * 16;
    uint32_t bHi = sb + bHiOff + (uint32_t)(colBase + nLoc) * bstB + bKb;
    uint32_t bLo = sb + bLoOff + (uint32_t)(colBase + nLoc) * bstB + bKb;

    gemm_pass<NPAIRS>(aHi, bHi, nk, bstB, c);
    gemm_pass<NPAIRS>(aHi, bLo, nk, bstB, c);
    gemm_pass<NPAIRS>(aLo, bHi, nk, bstB, c);
}

// Epilogue (N=128): bias + ReLU + hi/lo split -> act smem (stride 272 B)
__device__ __forceinline__ void epi128(char* smem, float c[][4],
                                       uint32_t biasOff, uint32_t hiOff, uint32_t loOff,
                                       int lane, int wm, int colBase) {
    int r0 = wm * 16 + (lane >> 2);
#pragma unroll
    for (int t = 0; t < 8; t++) {
        int n0 = colBase + t * 8 + (lane & 3) * 2;
        float2 bb = *(const float2*)(smem + biasOff + n0 * 4);
        {
            float v0 = fmaxf(c[t][0] + bb.x, 0.f);
            float v1 = fmaxf(c[t][1] + bb.y, 0.f);
            uint32_t hi, lo;
            split2(v0, v1, hi, lo);
            uint32_t o = (uint32_t)r0 * AST_H + (uint32_t)n0 * 2;
            *(uint32_t*)(smem + hiOff + o) = hi;
            *(uint32_t*)(smem + loOff + o) = lo;
        }
        {
            float v0 = fmaxf(c[t][2] + bb.x, 0.f);
            float v1 = fmaxf(c[t][3] + bb.y, 0.f);
            uint32_t hi, lo;
            split2(v0, v1, hi, lo);
            uint32_t o = (uint32_t)(r0 + 8) * AST_H + (uint32_t)n0 * 2;
            *(uint32_t*)(smem + hiOff + o) = hi;
            *(uint32_t*)(smem + loOff + o) = lo;
        }
    }
}

// ---------------------------------------------------------------------------
// mode: 0 = leaf (in=leaf_feats -> bufA), 1 = join A->B, 2 = join B->A
// ---------------------------------------------------------------------------
__global__ void __launch_bounds__(THREADS, 1)
level_kernel(const float* __restrict__ in,
             const float* __restrict__ W1, const float* __restrict__ b1,
             const float* __restrict__ W2, const float* __restrict__ b2,
             const float* __restrict__ W3, const float* __restrict__ b3,
             int K1, int logn, int off, int mode, int ntiles) {
    extern __shared__ char smem[];
    uint32_t sb = smem_u32(smem);
    int tid = threadIdx.x;
    int lane = tid & 31;
    int wid = tid >> 5;
    int wm = wid & 3;          // row group: wm*16
    int wn = wid >> 2;         // col group: wn*64 (L1/L2), wn*16 (L3)

    // --- weights (transposed [N][K], hi/lo split) + biases, once per CTA ---
    {
        // W1: [K1][128] -> W1T [128][K1], stride 208 B
        for (int i = tid; i < K1 * HD; i += THREADS) {
            int k = i / HD, n = i - k * HD;
            float v = W1[i];
            __nv_bfloat16 h = __float2bfloat16(v);
            __nv_bfloat16 l = __float2bfloat16(v - __bfloat162float(h));
            uint32_t o = (uint32_t)n * W1ST + (uint32_t)k * 2;
            *(__nv_bfloat16*)(smem + W1T_HI + o) = h;
            *(__nv_bfloat16*)(smem + W1T_LO + o) = l;
        }
        for (int i = tid; i < HD * HD; i += THREADS) {
            int k = i / HD, n = i - k * HD;
            float v = W2[i];
            __nv_bfloat16 h = __float2bfloat16(v);
            __nv_bfloat16 l = __float2bfloat16(v - __bfloat162float(h));
            uint32_t o = (uint32_t)n * W2ST + (uint32_t)k * 2;
            *(__nv_bfloat16*)(smem + W2T_HI + o) = h;
            *(__nv_bfloat16*)(smem + W2T_LO + o) = l;
        }
        for (int i = tid; i < HD * OD; i += THREADS) {
            int k = i / OD, n = i - k * OD;
            float v = W3[i];
            __nv_bfloat16 h = __float2bfloat16(v);
            __nv_bfloat16 l = __float2bfloat16(v - __bfloat162float(h));
            uint32_t o = (uint32_t)n * W3ST + (uint32_t)k * 2;
            *(__nv_bfloat16*)(smem + W3T_HI + o) = h;
            *(__nv_bfloat16*)(smem + W3T_LO + o) = l;
        }
        if (tid < HD) {
            ((float*)(smem + B1OFF))[tid] = b1[tid];
            ((float*)(smem + B2OFF))[tid] = b2[tid];
        }
        if (tid < OD) ((float*)(smem + B3OFF))[tid] = b3[tid];
    }
    __syncthreads();

    const float* prev = (mode == 1) ? g_bufA : g_bufB;
    float* dst = (mode == 0) ? g_bufA : ((mode == 1) ? g_bufB : g_bufA);
    const int n = 1 << logn;
    const int nk1 = K1 / 16;

    for (int t = blockIdx.x; t < ntiles; t += gridDim.x) {
        const int row0 = t * TILE_R;

        // ---- gather input tile, split hi/lo -> AA (stride 208 B) ----
        if (mode == 0) {
            const float2* src = (const float2*)(in + (size_t)row0 * FD);
#pragma unroll
            for (int i = tid; i < TILE_R * 16; i += THREADS) {
                int r = i >> 4, cp = i & 15;
                float2 v = src[i];
                uint32_t hi, lo;
                split2(v.x, v.y, hi, lo);
                uint32_t o = (uint32_t)r * AST_IN + (uint32_t)cp * 4;
                *(uint32_t*)(smem + AA_HI + o) = hi;
                *(uint32_t*)(smem + AA_LO + o) = lo;
            }
        } else {
#pragma unroll
            for (int i = tid; i < TILE_R * 48; i += THREADS) {
                int r = i / 48, cp = i - r * 48;
                int gr = row0 + r;
                int b = gr >> logn, ii = gr & (n - 1);
                float2 v;
                if (cp < 16)
                    v = *(const float2*)(in + (((size_t)b * (NLEAF - 1) + off + ii) << 5) + cp * 2);
                else
                    v = *(const float2*)(prev + (((size_t)(b << (logn + 1)) + 2 * ii) << 5) + (cp * 2 - 32));
                uint32_t hi, lo;
                split2(v.x, v.y, hi, lo);
                uint32_t o = (uint32_t)r * AST_IN + (uint32_t)cp * 4;
                *(uint32_t*)(smem + AA_HI + o) = hi;
                *(uint32_t*)(smem + AA_LO + o) = lo;
            }
        }
        __syncthreads();

        // ---- layer 1: AA[64 x K1] @ W1T -> AB[64 x 128] ----
        {
            float c[8][4];
            gemm3<4>(sb, AA_HI, AA_LO, AST_IN, W1T_HI, W1T_LO, W1ST,
                     nk1, wn * 64, lane, wm, c);
            epi128(smem, c, B1OFF, AB_HI, AB_LO, lane, wm, wn * 64);
        }
        __syncthreads();

        // ---- layer 2: AB[64 x 128] @ W2T -> AA[64 x 128] ----
        {
            float c[8][4];
            gemm3<4>(sb, AB_HI, AB_LO, AST_H, W2T_HI, W2T_LO, W2ST,
                     8, wn * 64, lane, wm, c);
            epi128(smem, c, B2OFF, AA_HI, AA_LO, lane, wm, wn * 64);
        }
        __syncthreads();

        // ---- layer 3: AA[64 x 128] @ W3T -> gmem fp32 [64 x 32] ----
        {
            float c[2][4];
            gemm3<1>(sb, AA_HI, AA_LO, AST_H, W3T_HI, W3T_LO, W3ST,
                     8, wn * 16, lane, wm, c);
            int r0 = row0 + wm * 16 + (lane >> 2);
#pragma unroll
            for (int tt = 0; tt < 2; tt++) {
                int n0 = wn * 16 + tt * 8 + (lane & 3) * 2;
                float2 bb = *(const float2*)(smem + B3OFF + n0 * 4);
                float2 v0 = make_float2(c[tt][0] + bb.x, c[tt][1] + bb.y);
                float2 v1 = make_float2(c[tt][2] + bb.x, c[tt][3] + bb.y);
                *(float2*)(dst + (size_t)r0 * OD + n0) = v0;
                *(float2*)(dst + (size_t)(r0 + 8) * OD + n0) = v1;
            }
        }
        __syncthreads();
    }
}

// ---------------------------------------------------------------------------
__global__ void extract_kernel(float* __restrict__ out) {
    int b = blockIdx.x * blockDim.x + threadIdx.x;
    if (b < NB) out[b] = g_bufA[(size_t)b * OD];
}

// ---------------------------------------------------------------------------
extern "C" void kernel_launch(void* const* d_in, const int* in_sizes, int n_in,
                              void* d_out, int out_size) {
    const float* leaf_feats = (const float*)d_in[0];
    const float* internal   = (const float*)d_in[1];
    const float* sW1 = (const float*)d_in[2];
    const float* sb1 = (const float*)d_in[3];
    const float* sW2 = (const float*)d_in[4];
    const float* sb2 = (const float*)d_in[5];
    const float* sW3 = (const float*)d_in[6];
    const float* sb3 = (const float*)d_in[7];
    const float* jW1 = (const float*)d_in[8];
    const float* jb1 = (const float*)d_in[9];
    const float* jW2 = (const float*)d_in[10];
    const float* jb2 = (const float*)d_in[11];
    const float* jW3 = (const float*)d_in[12];
    const float* jb3 = (const float*)d_in[13];
    float* out = (float*)d_out;

    cudaFuncSetAttribute(level_kernel, cudaFuncAttributeMaxDynamicSharedMemorySize, SMEM_TOTAL);

    // Leaf level: K1 = 32, dst = bufA
    {
        int ntiles = (NB * NLEAF) / TILE_R;     // 32768
        int grid = ntiles < 148 ? ntiles : 148;
        level_kernel<<<grid, THREADS, SMEM_TOTAL>>>(
            leaf_feats, sW1, sb1, sW2, sb2, sW3, sb3,
            FD, 0, 0, /*mode=*/0, ntiles);
    }

    // Join levels n = 512..1; mode alternates 1 (A->B), 2 (B->A); final in bufA
    int off = 0;
    int mode = 1;
    for (int logn = 9; logn >= 0; --logn) {
        int n = 1 << logn;
        int ntiles = (NB * n) / TILE_R;
        int grid = ntiles < 148 ? ntiles : 148;
        level_kernel<<<grid, THREADS, SMEM_TOTAL>>>(
            internal, jW1, jb1, jW2, jb2, jW3, jb3,
            FD + 2 * OD, logn, off, mode, ntiles);
        off += n;
        mode = (mode == 1) ? 2 : 1;
    }

    extract_kernel<<<(NB + 255) / 256, 256>>>(out);
}

// round 4
// speedup vs baseline: 3.1375x; 1.2231x over previous
#include <cuda_runtime.h>
#include <cuda_bf16.h>
#include <cstdint>

// ---------------------------------------------------------------------------
// PlanStructuredNetwork via mma.sync bf16 (fp32 acc), bf16x3 split.
// R4: 512 threads (16 warps -> 4/SMSP), k-restructured 3-pass loop
// (A hi/lo + B hi/lo loaded once per k-chunk -> 33% fewer LDSM),
// kernels templated on (NK1, MODE) for full unroll.
//   Leaf:  (B*1024, 32) -> 128 -> 128 -> 32
//   Join x10: (B*n, 96) -> 128 -> 128 -> 32,  n = 512..1
// ---------------------------------------------------------------------------

#define NB    2048
#define NLEAF 1024
#define FD    32
#define HD    128
#define OD    32

#define TILE_R  64
#define THREADS 512

__device__ float g_bufA[(size_t)NB * NLEAF * OD];        // 268 MB
__device__ float g_bufB[(size_t)NB * (NLEAF / 2) * OD];  // 134 MB

// --- smem byte offsets ---
#define AA_HI   0           // X: 64 rows * 208 B
#define AA_LO   17408       // (X region padded to 17408 each for alignment)
#define AB_HI   34816       // H: 64 rows * 272 B = 17408
#define AB_LO   52224
#define W1T_HI  69632       // [128][104] bf16 = 26624 B
#define W1T_LO  96256
#define W2T_HI  122880      // [128][136] bf16 = 34816 B
#define W2T_LO  157696
#define W3T_HI  192512      // [32][136] bf16 = 8704 B
#define W3T_LO  201216
#define B1OFF   209920
#define B2OFF   210432
#define B3OFF   210944
#define SMEM_TOTAL 211072

#define AST_IN  208         // X row stride (104 bf16; step 52 words ≡ conflict-free)
#define AST_H   272         // H row stride (136 bf16; step 68 words ≡ conflict-free)
#define W1ST    208
#define W2ST    272
#define W3ST    272

// ---------------------------------------------------------------------------
__device__ __forceinline__ uint32_t smem_u32(const void* p) {
    uint32_t a;
    asm("{ .reg .u64 t; cvta.to.shared.u64 t, %1; cvt.u32.u64 %0, t; }"
        : "=r"(a) : "l"(p));
    return a;
}

#define LDSM_X4(r0, r1, r2, r3, addr)                                          \
    asm volatile("ldmatrix.sync.aligned.m8n8.x4.shared.b16 {%0,%1,%2,%3}, [%4];" \
                 : "=r"(r0), "=r"(r1), "=r"(r2), "=r"(r3) : "r"(addr))

#define LDSM_X2(r0, r1, addr)                                                  \
    asm volatile("ldmatrix.sync.aligned.m8n8.x2.shared.b16 {%0,%1}, [%2];"     \
                 : "=r"(r0), "=r"(r1) : "r"(addr))

#define MMA_BF16(c, a0, a1, a2, a3, b0, b1)                                    \
    asm volatile("mma.sync.aligned.m16n8k16.row.col.f32.bf16.bf16.f32 "        \
                 "{%0,%1,%2,%3}, {%4,%5,%6,%7}, {%8,%9}, {%0,%1,%2,%3};"       \
                 : "+f"((c)[0]), "+f"((c)[1]), "+f"((c)[2]), "+f"((c)[3])      \
                 : "r"(a0), "r"(a1), "r"(a2), "r"(a3), "r"(b0), "r"(b1))

__device__ __forceinline__ void split2(float v0, float v1, uint32_t& hi, uint32_t& lo) {
    __nv_bfloat16 h0 = __float2bfloat16(v0);
    __nv_bfloat16 h1 = __float2bfloat16(v1);
    float r0 = v0 - __bfloat162float(h0);
    float r1 = v1 - __bfloat162float(h1);
    __nv_bfloat16 l0 = __float2bfloat16(r0);
    __nv_bfloat16 l1 = __float2bfloat16(r1);
    hi = (uint32_t)__bfloat16_as_ushort(h0) | ((uint32_t)__bfloat16_as_ushort(h1) << 16);
    lo = (uint32_t)__bfloat16_as_ushort(l0) | ((uint32_t)__bfloat16_as_ushort(l1) << 16);
}

// ---------------------------------------------------------------------------
// bf16x3 GEMM, x4 B loads: warp computes 16 rows x (NT2*16) cols.
// Per k-chunk: load Ahi/Alo (x4), per pair Bhi/Blo (x4), 6 MMAs per pair.
// C = Ahi*Bhi + Ahi*Blo + Alo*Bhi
// ---------------------------------------------------------------------------
template <int NT2, int NK>
__device__ __forceinline__ void gemm3_x4(uint32_t sb,
                                         uint32_t aHiOff, uint32_t aLoOff, int astB,
                                         uint32_t bHiOff, uint32_t bLoOff, int bstB,
                                         int colBase, int lane, int wm,
                                         float c[][4]) {
#pragma unroll
    for (int j = 0; j < 2 * NT2; j++)
#pragma unroll
        for (int q = 0; q < 4; q++) c[j][q] = 0.f;

    const int aRow = wm * 16 + (lane & 15);
    const uint32_t aKb = (uint32_t)(lane >> 4) * 16;
    const uint32_t aHi = sb + aHiOff + (uint32_t)aRow * astB + aKb;
    const uint32_t aLo = sb + aLoOff + (uint32_t)aRow * astB + aKb;

    const int nLoc = (lane & 7) + ((lane >> 4) << 3);
    const uint32_t bKb = (uint32_t)((lane >> 3) & 1) * 16;
    const uint32_t bHi = sb + bHiOff + (uint32_t)(colBase + nLoc) * bstB + bKb;
    const uint32_t bLo = sb + bLoOff + (uint32_t)(colBase + nLoc) * bstB + bKb;

#pragma unroll
    for (int k = 0; k < NK; k++) {
        uint32_t ah0, ah1, ah2, ah3, al0, al1, al2, al3;
        LDSM_X4(ah0, ah1, ah2, ah3, aHi + k * 32);
        LDSM_X4(al0, al1, al2, al3, aLo + k * 32);
#pragma unroll
        for (int j = 0; j < NT2; j++) {
            uint32_t bh0, bh1, bh2, bh3, bl0, bl1, bl2, bl3;
            LDSM_X4(bh0, bh1, bh2, bh3, bHi + j * 16 * bstB + k * 32);
            LDSM_X4(bl0, bl1, bl2, bl3, bLo + j * 16 * bstB + k * 32);
            MMA_BF16(c[2 * j],     ah0, ah1, ah2, ah3, bh0, bh1);
            MMA_BF16(c[2 * j + 1], ah0, ah1, ah2, ah3, bh2, bh3);
            MMA_BF16(c[2 * j],     ah0, ah1, ah2, ah3, bl0, bl1);
            MMA_BF16(c[2 * j + 1], ah0, ah1, ah2, ah3, bl2, bl3);
            MMA_BF16(c[2 * j],     al0, al1, al2, al3, bh0, bh1);
            MMA_BF16(c[2 * j + 1], al0, al1, al2, al3, bh2, bh3);
        }
    }
}

// bf16x3 GEMM, x2 B loads: warp computes 16 rows x (NT*8) cols (L3).
template <int NT, int NK>
__device__ __forceinline__ void gemm3_x2(uint32_t sb,
                                         uint32_t aHiOff, uint32_t aLoOff, int astB,
                                         uint32_t bHiOff, uint32_t bLoOff, int bstB,
                                         int colBase, int lane, int wm,
                                         float c[][4]) {
#pragma unroll
    for (int j = 0; j < NT; j++)
#pragma unroll
        for (int q = 0; q < 4; q++) c[j][q] = 0.f;

    const int aRow = wm * 16 + (lane & 15);
    const uint32_t aKb = (uint32_t)(lane >> 4) * 16;
    const uint32_t aHi = sb + aHiOff + (uint32_t)aRow * astB + aKb;
    const uint32_t aLo = sb + aLoOff + (uint32_t)aRow * astB + aKb;

    const int l15 = lane & 15;
    const int nIdx = l15 & 7;
    const uint32_t bKb = (uint32_t)(l15 >> 3) * 16;
    const uint32_t bHi = sb + bHiOff + (uint32_t)(colBase + nIdx) * bstB + bKb;
    const uint32_t bLo = sb + bLoOff + (uint32_t)(colBase + nIdx) * bstB + bKb;

#pragma unroll
    for (int k = 0; k < NK; k++) {
        uint32_t ah0, ah1, ah2, ah3, al0, al1, al2, al3;
        LDSM_X4(ah0, ah1, ah2, ah3, aHi + k * 32);
        LDSM_X4(al0, al1, al2, al3, aLo + k * 32);
#pragma unroll
        for (int j = 0; j < NT; j++) {
            uint32_t bh0, bh1, bl0, bl1;
            LDSM_X2(bh0, bh1, bHi + j * 8 * bstB + k * 32);
            LDSM_X2(bl0, bl1, bLo + j * 8 * bstB + k * 32);
            MMA_BF16(c[j], ah0, ah1, ah2, ah3, bh0, bh1);
            MMA_BF16(c[j], ah0, ah1, ah2, ah3, bl0, bl1);
            MMA_BF16(c[j], al0, al1, al2, al3, bh0, bh1);
        }
    }
}

// Epilogue (N=128, warp covers 32 cols): bias + ReLU + split -> act smem
__device__ __forceinline__ void epi128(char* smem, float c[][4],
                                       uint32_t biasOff, uint32_t hiOff, uint32_t loOff,
                                       int lane, int wm, int colBase) {
    int r0 = wm * 16 + (lane >> 2);
#pragma unroll
    for (int t = 0; t < 4; t++) {
        int n0 = colBase + t * 8 + (lane & 3) * 2;
        float2 bb = *(const float2*)(smem + biasOff + n0 * 4);
        {
            float v0 = fmaxf(c[t][0] + bb.x, 0.f);
            float v1 = fmaxf(c[t][1] + bb.y, 0.f);
            uint32_t hi, lo;
            split2(v0, v1, hi, lo);
            uint32_t o = (uint32_t)r0 * AST_H + (uint32_t)n0 * 2;
            *(uint32_t*)(smem + hiOff + o) = hi;
            *(uint32_t*)(smem + loOff + o) = lo;
        }
        {
            float v0 = fmaxf(c[t][2] + bb.x, 0.f);
            float v1 = fmaxf(c[t][3] + bb.y, 0.f);
            uint32_t hi, lo;
            split2(v0, v1, hi, lo);
            uint32_t o = (uint32_t)(r0 + 8) * AST_H + (uint32_t)n0 * 2;
            *(uint32_t*)(smem + hiOff + o) = hi;
            *(uint32_t*)(smem + loOff + o) = lo;
        }
    }
}

// ---------------------------------------------------------------------------
// MODE: 0 = leaf (in -> bufA), 1 = join A->B, 2 = join B->A
// NK1:  K1/16 (2 for leaf, 6 for join)
// ---------------------------------------------------------------------------
template <int NK1, int MODE>
__global__ void __launch_bounds__(THREADS, 1)
level_kernel(const float* __restrict__ in,
             const float* __restrict__ W1, const float* __restrict__ b1,
             const float* __restrict__ W2, const float* __restrict__ b2,
             const float* __restrict__ W3, const float* __restrict__ b3,
             int logn, int off, int ntiles) {
    extern __shared__ char smem[];
    uint32_t sb = smem_u32(smem);
    const int tid = threadIdx.x;
    const int lane = tid & 31;
    const int wid = tid >> 5;
    const int wm = wid & 3;        // rows wm*16
    const int wn = wid >> 2;       // col group 0..3 (32 cols each for L1/L2)
    const int K1 = NK1 * 16;

    // --- weights (transposed [N][K], hi/lo) + biases, once per CTA ---
    for (int i = tid; i < K1 * HD; i += THREADS) {
        int k = i / HD, n = i - k * HD;
        float v = W1[i];
        __nv_bfloat16 h = __float2bfloat16(v);
        __nv_bfloat16 l = __float2bfloat16(v - __bfloat162float(h));
        uint32_t o = (uint32_t)n * W1ST + (uint32_t)k * 2;
        *(__nv_bfloat16*)(smem + W1T_HI + o) = h;
        *(__nv_bfloat16*)(smem + W1T_LO + o) = l;
    }
    for (int i = tid; i < HD * HD; i += THREADS) {
        int k = i / HD, n = i - k * HD;
        float v = W2[i];
        __nv_bfloat16 h = __float2bfloat16(v);
        __nv_bfloat16 l = __float2bfloat16(v - __bfloat162float(h));
        uint32_t o = (uint32_t)n * W2ST + (uint32_t)k * 2;
        *(__nv_bfloat16*)(smem + W2T_HI + o) = h;
        *(__nv_bfloat16*)(smem + W2T_LO + o) = l;
    }
    for (int i = tid; i < HD * OD; i += THREADS) {
        int k = i / OD, n = i - k * OD;
        float v = W3[i];
        __nv_bfloat16 h = __float2bfloat16(v);
        __nv_bfloat16 l = __float2bfloat16(v - __bfloat162float(h));
        uint32_t o = (uint32_t)n * W3ST + (uint32_t)k * 2;
        *(__nv_bfloat16*)(smem + W3T_HI + o) = h;
        *(__nv_bfloat16*)(smem + W3T_LO + o) = l;
    }
    if (tid < HD) {
        ((float*)(smem + B1OFF))[tid] = b1[tid];
        ((float*)(smem + B2OFF))[tid] = b2[tid];
    }
    if (tid < OD) ((float*)(smem + B3OFF))[tid] = b3[tid];
    __syncthreads();

    const float* prev = (MODE == 1) ? g_bufA : g_bufB;
    float* dst = (MODE == 0) ? g_bufA : ((MODE == 1) ? g_bufB : g_bufA);
    const int n = 1 << logn;

    for (int t = blockIdx.x; t < ntiles; t += gridDim.x) {
        const int row0 = t * TILE_R;

        // ---- gather input tile, split hi/lo -> AA ----
        if (MODE == 0) {
            const float2* src = (const float2*)(in + (size_t)row0 * FD);
#pragma unroll
            for (int i = tid; i < TILE_R * 16; i += THREADS) {
                int r = i >> 4, cp = i & 15;
                float2 v = src[i];
                uint32_t hi, lo;
                split2(v.x, v.y, hi, lo);
                uint32_t o = (uint32_t)r * AST_IN + (uint32_t)cp * 4;
                *(uint32_t*)(smem + AA_HI + o) = hi;
                *(uint32_t*)(smem + AA_LO + o) = lo;
            }
        } else {
#pragma unroll
            for (int i = tid; i < TILE_R * 48; i += THREADS) {
                int r = i / 48, cp = i - r * 48;
                int gr = row0 + r;
                int b = gr >> logn, ii = gr & (n - 1);
                float2 v;
                if (cp < 16)
                    v = *(const float2*)(in + (((size_t)b * (NLEAF - 1) + off + ii) << 5) + cp * 2);
                else
                    v = *(const float2*)(prev + (((size_t)(b << (logn + 1)) + 2 * ii) << 5) + (cp * 2 - 32));
                uint32_t hi, lo;
                split2(v.x, v.y, hi, lo);
                uint32_t o = (uint32_t)r * AST_IN + (uint32_t)cp * 4;
                *(uint32_t*)(smem + AA_HI + o) = hi;
                *(uint32_t*)(smem + AA_LO + o) = lo;
            }
        }
        __syncthreads();

        // ---- layer 1: AA[64 x K1] @ W1T -> AB[64 x 128] ----
        {
            float c[4][4];
            gemm3_x4<2, NK1>(sb, AA_HI, AA_LO, AST_IN, W1T_HI, W1T_LO, W1ST,
                             wn * 32, lane, wm, c);
            epi128(smem, c, B1OFF, AB_HI, AB_LO, lane, wm, wn * 32);
        }
        __syncthreads();

        // ---- layer 2: AB[64 x 128] @ W2T -> AA[64 x 128] ----
        {
            float c[4][4];
            gemm3_x4<2, 8>(sb, AB_HI, AB_LO, AST_H, W2T_HI, W2T_LO, W2ST,
                           wn * 32, lane, wm, c);
            epi128(smem, c, B2OFF, AA_HI, AA_LO, lane, wm, wn * 32);
        }
        __syncthreads();

        // ---- layer 3: AA[64 x 128] @ W3T -> gmem fp32 [64 x 32] ----
        if (wn < 2) {
            float c[2][4];
            gemm3_x2<2, 8>(sb, AA_HI, AA_LO, AST_H, W3T_HI, W3T_LO, W3ST,
                           wn * 16, lane, wm, c);
            int r0 = row0 + wm * 16 + (lane >> 2);
#pragma unroll
            for (int tt = 0; tt < 2; tt++) {
                int n0 = wn * 16 + tt * 8 + (lane & 3) * 2;
                float2 bb = *(const float2*)(smem + B3OFF + n0 * 4);
                float2 v0 = make_float2(c[tt][0] + bb.x, c[tt][1] + bb.y);
                float2 v1 = make_float2(c[tt][2] + bb.x, c[tt][3] + bb.y);
                *(float2*)(dst + (size_t)r0 * OD + n0) = v0;
                *(float2*)(dst + (size_t)(r0 + 8) * OD + n0) = v1;
            }
        }
        __syncthreads();
    }
}

// ---------------------------------------------------------------------------
__global__ void extract_kernel(float* __restrict__ out) {
    int b = blockIdx.x * blockDim.x + threadIdx.x;
    if (b < NB) out[b] = g_bufA[(size_t)b * OD];
}

// ---------------------------------------------------------------------------
extern "C" void kernel_launch(void* const* d_in, const int* in_sizes, int n_in,
                              void* d_out, int out_size) {
    const float* leaf_feats = (const float*)d_in[0];
    const float* internal   = (const float*)d_in[1];
    const float* sW1 = (const float*)d_in[2];
    const float* sb1 = (const float*)d_in[3];
    const float* sW2 = (const float*)d_in[4];
    const float* sb2 = (const float*)d_in[5];
    const float* sW3 = (const float*)d_in[6];
    const float* sb3 = (const float*)d_in[7];
    const float* jW1 = (const float*)d_in[8];
    const float* jb1 = (const float*)d_in[9];
    const float* jW2 = (const float*)d_in[10];
    const float* jb2 = (const float*)d_in[11];
    const float* jW3 = (const float*)d_in[12];
    const float* jb3 = (const float*)d_in[13];
    float* out = (float*)d_out;

    cudaFuncSetAttribute(level_kernel<2, 0>, cudaFuncAttributeMaxDynamicSharedMemorySize, SMEM_TOTAL);
    cudaFuncSetAttribute(level_kernel<6, 1>, cudaFuncAttributeMaxDynamicSharedMemorySize, SMEM_TOTAL);
    cudaFuncSetAttribute(level_kernel<6, 2>, cudaFuncAttributeMaxDynamicSharedMemorySize, SMEM_TOTAL);

    // Leaf level: K1 = 32, dst = bufA
    {
        int ntiles = (NB * NLEAF) / TILE_R;     // 32768
        int grid = ntiles < 148 ? ntiles : 148;
        level_kernel<2, 0><<<grid, THREADS, SMEM_TOTAL>>>(
            leaf_feats, sW1, sb1, sW2, sb2, sW3, sb3, 0, 0, ntiles);
    }

    // Join levels n = 512..1; alternate A->B / B->A; final lands in bufA
    int off = 0;
    int mode = 1;
    for (int logn = 9; logn >= 0; --logn) {
        int n = 1 << logn;
        int ntiles = (NB * n) / TILE_R;
        int grid = ntiles < 148 ? ntiles : 148;
        if (mode == 1)
            level_kernel<6, 1><<<grid, THREADS, SMEM_TOTAL>>>(
                internal, jW1, jb1, jW2, jb2, jW3, jb3, logn, off, ntiles);
        else
            level_kernel<6, 2><<<grid, THREADS, SMEM_TOTAL>>>(
                internal, jW1, jb1, jW2, jb2, jW3, jb3, logn, off, ntiles);
        off += n;
        mode = (mode == 1) ? 2 : 1;
    }

    extract_kernel<<<(NB + 255) / 256, 256>>>(out);
}